// round 14
// baseline (speedup 1.0000x reference)
#include <cuda_runtime.h>

// Problem constants
#define NB     4
#define NP     1024
#define NKN    32
#define DIMC   256
#define HEADS  8
#define DH     64
#define DPG    32
#define INNERD 512
#define NPTS   (NB*NP)        // 4096 points
#define NTOK   (NPTS*NKN)     // 131072 tokens
#define NKT    (INNERD/8)     // 64 k-tiles

// ---------------- device scratch (no allocations allowed) ----------------
__device__ float g_sum[DIMC];
__device__ float g_sumsq[DIMC];
__device__ float g_scale[DIMC];
__device__ float g_shift[DIMC];
// Wout in mma B-fragment order: [ntile(32)][ktile(64)][lane] float2 (tf32-rounded)
// float2 = { (k=kt*8+tg, n=nt*8+g4), (k=kt*8+tg+4, same n) }
__device__ float2 g_woutF[32 * NKT * 32];         // 512 KB
// QKV weights in mma-fragment order: [h][pr][ntile(8)][kt(4)][lane(32)][2]
#define WFRAG_FLOATS (HEADS*3*8*4*32*2)           // 49152
__device__ float g_wfrag[WFRAG_FLOATS];

// ---------------- tf32 / mma helpers ----------------
__device__ __forceinline__ float tf32r(float x) {
    unsigned u; asm("cvt.rna.tf32.f32 %0, %1;" : "=r"(u) : "f"(x));
    return __uint_as_float(u);
}
__device__ __forceinline__ unsigned fbits(float x) { return __float_as_uint(x); }

__device__ __forceinline__ void mma_tf32(float c[4], const unsigned a[4], const unsigned b[2]) {
    asm volatile("mma.sync.aligned.m16n8k8.row.col.f32.tf32.tf32.f32 "
                 "{%0,%1,%2,%3}, {%4,%5,%6,%7}, {%8,%9}, {%0,%1,%2,%3};"
                 : "+f"(c[0]), "+f"(c[1]), "+f"(c[2]), "+f"(c[3])
                 : "r"(a[0]), "r"(a[1]), "r"(a[2]), "r"(a[3]), "r"(b[0]), "r"(b[1]));
}

// ---------------- K0: zero BN accumulators ----------------
__global__ void bn_zero_kernel() {
    g_sum[threadIdx.x] = 0.f;
    g_sumsq[threadIdx.x] = 0.f;
}

// ---------------- K1: BN statistics ----------------
__global__ __launch_bounds__(256) void bn_stats_kernel(const float4* __restrict__ x4) {
    const int tid = threadIdx.x;
    const int c64 = tid & 63;
    const int rl  = tid >> 6;
    const size_t base = (size_t)blockIdx.x * 256 + (size_t)rl * 64;
    float4 s = make_float4(0.f,0.f,0.f,0.f);
    float4 q = make_float4(0.f,0.f,0.f,0.f);
    #pragma unroll 4
    for (int i = 0; i < 64; ++i) {
        float4 v = x4[(base + i) * 64 + c64];
        s.x += v.x; s.y += v.y; s.z += v.z; s.w += v.w;
        q.x += v.x*v.x; q.y += v.y*v.y; q.z += v.z*v.z; q.w += v.w*v.w;
    }
    __shared__ float4 ss[256], qq[256];
    ss[tid] = s; qq[tid] = q;
    __syncthreads();
    if (tid < 64) {
        float4 a = ss[tid], b = ss[tid+64], c2 = ss[tid+128], d = ss[tid+192];
        float4 e = qq[tid], f = qq[tid+64], g2 = qq[tid+128], h = qq[tid+192];
        atomicAdd(&g_sum[tid*4+0], a.x+b.x+c2.x+d.x);
        atomicAdd(&g_sum[tid*4+1], a.y+b.y+c2.y+d.y);
        atomicAdd(&g_sum[tid*4+2], a.z+b.z+c2.z+d.z);
        atomicAdd(&g_sum[tid*4+3], a.w+b.w+c2.w+d.w);
        atomicAdd(&g_sumsq[tid*4+0], e.x+f.x+g2.x+h.x);
        atomicAdd(&g_sumsq[tid*4+1], e.y+f.y+g2.y+h.y);
        atomicAdd(&g_sumsq[tid*4+2], e.z+f.z+g2.z+h.z);
        atomicAdd(&g_sumsq[tid*4+3], e.w+f.w+g2.w+h.w);
    }
}

// ---------------- K2: BN finalize ----------------
__global__ void bn_finalize_kernel(const float* __restrict__ gamma,
                                   const float* __restrict__ beta) {
    const int c = threadIdx.x;
    const float invN = 1.f / (float)NTOK;
    float m   = g_sum[c] * invN;
    float var = g_sumsq[c] * invN - m * m;
    float rstd = rsqrtf(var + 1e-5f);
    float sc = gamma[c] * rstd;
    g_scale[c] = sc;
    g_shift[c] = beta[c] - m * sc;
}

// ---------------- K2b: pre-round weights; build fragment layouts ----------------
__global__ void round_weights_kernel(const float* __restrict__ Wq,
                                     const float* __restrict__ Wk,
                                     const float* __restrict__ Wv,
                                     const float* __restrict__ Wout) {
    int i = blockIdx.x * 256 + threadIdx.x;
    if (i < INNERD*DIMC) {
        int e    = i & 1;
        int lane = (i >> 1) & 31;
        int kt   = (i >> 6) & 63;
        int nt   = (i >> 12) & 31;
        int k = kt*8 + (lane & 3) + (e ? 4 : 0);
        int n = nt*8 + (lane >> 2);
        ((float*)g_woutF)[i] = tf32r(Wout[k*DIMC + n]);
    }
    if (i < WFRAG_FLOATS) {
        int e    = i & 1;
        int lane = (i >> 1) & 31;
        int kt   = (i >> 6) & 3;
        int nt   = (i >> 8) & 7;
        int pr   = (i >> 11) % 3;
        int h    = i / (3 << 11);
        int o = nt*8 + (lane >> 2);
        int c = kt*8 + (lane & 3) + (e ? 4 : 0);
        const float* src = (pr == 0) ? Wq : (pr == 1) ? Wk : Wv;
        g_wfrag[i] = tf32r(src[h*(DH*DPG) + o*DPG + c]);
    }
}

// ---------------- K3: fully fused BN + QKV + attention + y-GEMM ----------------
// Block = 1 point (32 tokens), 256 threads = 8 warps, occ 2 (yacc regs).
// smem floats: xh 32*36 + qs 32*68 + ks 32*68 + vT 64*36 + attnS 32*36 + oh 32*68 = 11136
#define FUSED_SMEM_BYTES (11136 * 4)               // 44544 B

__global__ __launch_bounds__(256, 2) void fused_all_kernel(
    const float* __restrict__ x,
    const float* __restrict__ bout,
    float* __restrict__ y)
{
    extern __shared__ float sm[];
    float* xh    = sm;                 // [32][36]
    float* qs    = xh + 32*36;         // [32][68]
    float* ks    = qs + 32*68;         // [32][68]
    float* vT    = ks + 32*68;         // [64 out][36]
    float* attnS = vT + 64*36;         // [32][36]
    float* oh    = attnS + 32*36;      // [32][68] per-head AV output

    const int tid  = threadIdx.x;
    const int warp = tid >> 5;
    const int lane = tid & 31;
    const int g4   = lane >> 2;
    const int tg   = lane & 3;
    const size_t tok0 = (size_t)blockIdx.x * NKN;

    float yacc[2][4][4] = {};          // warp n-slice = warp*32 .. +32 ; m = 32 rows

    for (int h = 0; h < HEADS; ++h) {
        // ---- stage xh (normalize + tf32): 1024 elems / 256 threads ----
        #pragma unroll
        for (int j = 0; j < 4; ++j) {
            int i = tid + j*256;
            int tk = i >> 5, c = i & 31;
            float sc = g_scale[h*32 + c];
            float sh = g_shift[h*32 + c];
            xh[tk*36 + c] = tf32r(fmaf(x[(tok0 + tk)*DIMC + h*32 + c], sc, sh));
        }
        __syncthreads();   // xh ready; also orders prior y-gemm oh reads vs nothing (oh safe)

        // ---- projections: warp = ntile (8 out cols); M=32 (2 mtiles) ----
        {
            unsigned a[2][4][4];
            #pragma unroll
            for (int mt = 0; mt < 2; ++mt)
                #pragma unroll
                for (int kt = 0; kt < 4; ++kt) {
                    const float* ap = &xh[(mt*16 + g4)*36 + kt*8 + tg];
                    a[mt][kt][0] = fbits(ap[0]);
                    a[mt][kt][1] = fbits(ap[8*36]);
                    a[mt][kt][2] = fbits(ap[4]);
                    a[mt][kt][3] = fbits(ap[8*36 + 4]);
                }
            const int col = warp*8 + 2*tg;
            #pragma unroll
            for (int pr = 0; pr < 3; ++pr) {
                unsigned b[4][2];
                #pragma unroll
                for (int kt = 0; kt < 4; ++kt) {
                    const float2 v = *(const float2*)
                        &g_wfrag[((((h*3 + pr)*8 + warp)*4 + kt)*32 + lane)*2];
                    b[kt][0] = fbits(v.x);
                    b[kt][1] = fbits(v.y);
                }
                float c[2][4] = {};
                #pragma unroll
                for (int kt = 0; kt < 4; ++kt) {
                    mma_tf32(c[0], a[0][kt], b[kt]);
                    mma_tf32(c[1], a[1][kt], b[kt]);
                }
                if (pr < 2) {
                    float* dst = (pr == 0) ? qs : ks;
                    #pragma unroll
                    for (int mt = 0; mt < 2; ++mt) {
                        int r = mt*16 + g4;
                        *(float2*)&dst[r*68 + col]     = make_float2(tf32r(c[mt][0]), tf32r(c[mt][1]));
                        *(float2*)&dst[(r+8)*68 + col] = make_float2(tf32r(c[mt][2]), tf32r(c[mt][3]));
                    }
                } else {
                    #pragma unroll
                    for (int mt = 0; mt < 2; ++mt) {
                        int r = mt*16 + g4;
                        vT[(col  )*36 + r]     = tf32r(c[mt][0]);
                        vT[(col+1)*36 + r]     = tf32r(c[mt][1]);
                        vT[(col  )*36 + r + 8] = tf32r(c[mt][2]);
                        vT[(col+1)*36 + r + 8] = tf32r(c[mt][3]);
                    }
                }
            }
        }
        __syncthreads();

        // ---- dots: warp -> (mt = w>>2, nt = w&3); K=64 (8 ktiles) ----
        {
            const int mt = warp >> 2, nt = warp & 3;
            float c[4] = {};
            #pragma unroll
            for (int kt = 0; kt < 8; ++kt) {
                const float* ap = &qs[(mt*16 + g4)*68 + kt*8 + tg];
                unsigned a[4] = { fbits(ap[0]), fbits(ap[8*68]), fbits(ap[4]), fbits(ap[8*68+4]) };
                const float* bp = &ks[(nt*8 + g4)*68 + kt*8 + tg];
                unsigned b[2] = { fbits(bp[0]), fbits(bp[4]) };
                mma_tf32(c, a, b);
            }
            const int r0 = mt*16 + g4, col = nt*8 + 2*tg;
            *(float2*)&attnS[r0*36 + col]     = make_float2(c[0]*0.125f, c[1]*0.125f);
            *(float2*)&attnS[(r0+8)*36 + col] = make_float2(c[2]*0.125f, c[3]*0.125f);
        }
        __syncthreads();

        // ---- softmax: warp owns rows warp*4..+4; 8 lanes per row ----
        {
            const int r  = warp*4 + (lane >> 3);
            const int jb = lane & 7;
            float dv[4];
            #pragma unroll
            for (int u = 0; u < 4; ++u) dv[u] = attnS[r*36 + jb + 8*u];
            float mx = fmaxf(fmaxf(dv[0], dv[1]), fmaxf(dv[2], dv[3]));
            mx = fmaxf(mx, __shfl_xor_sync(0xffffffffu, mx, 1));
            mx = fmaxf(mx, __shfl_xor_sync(0xffffffffu, mx, 2));
            mx = fmaxf(mx, __shfl_xor_sync(0xffffffffu, mx, 4));
            float ev[4], s = 0.f;
            #pragma unroll
            for (int u = 0; u < 4; ++u) { ev[u] = __expf(dv[u] - mx); s += ev[u]; }
            s += __shfl_xor_sync(0xffffffffu, s, 1);
            s += __shfl_xor_sync(0xffffffffu, s, 2);
            s += __shfl_xor_sync(0xffffffffu, s, 4);
            float inv = 1.f / s;
            #pragma unroll
            for (int u = 0; u < 4; ++u) attnS[r*36 + jb + 8*u] = tf32r(ev[u] * inv);
        }
        __syncthreads();

        // ---- AV: warp -> (mt = w>>2, 16-col slice = w&3); writes oh[32][68] ----
        {
            const int mt = warp >> 2;
            unsigned a[4][4];
            #pragma unroll
            for (int kt = 0; kt < 4; ++kt) {
                const float* ap = &attnS[(mt*16 + g4)*36 + kt*8 + tg];
                a[kt][0] = fbits(ap[0]);
                a[kt][1] = fbits(ap[8*36]);
                a[kt][2] = fbits(ap[4]);
                a[kt][3] = fbits(ap[8*36 + 4]);
            }
            #pragma unroll
            for (int nn = 0; nn < 2; ++nn) {
                const int o = (warp & 3)*16 + nn*8;
                float c[4] = {};
                #pragma unroll
                for (int kt = 0; kt < 4; ++kt) {
                    const float* bp = &vT[(o + g4)*36 + kt*8 + tg];
                    unsigned b[2] = { fbits(bp[0]), fbits(bp[4]) };
                    mma_tf32(c, a[kt], b);
                }
                const int r = mt*16 + g4, col = o + 2*tg;
                *(float2*)&oh[r*68 + col]     = make_float2(tf32r(c[0]), tf32r(c[1]));
                *(float2*)&oh[(r+8)*68 + col] = make_float2(tf32r(c[2]), tf32r(c[3]));
            }
        }
        __syncthreads();   // oh complete for this head

        // ---- y-GEMM accumulate: yacc += oh[32,64] @ Wout[h*64:(h+1)*64, warp n-slice] ----
        {
            const int nt_base = warp*4;            // global ntile of warp's slice
            #pragma unroll
            for (int kt = 0; kt < 8; ++kt) {
                const int ktg = h*8 + kt;
                unsigned a[2][4];
                #pragma unroll
                for (int mt = 0; mt < 2; ++mt) {
                    const float* ap = &oh[(mt*16 + g4)*68 + kt*8 + tg];
                    a[mt][0] = fbits(ap[0]);
                    a[mt][1] = fbits(ap[8*68]);
                    a[mt][2] = fbits(ap[4]);
                    a[mt][3] = fbits(ap[8*68 + 4]);
                }
                #pragma unroll
                for (int nt = 0; nt < 4; ++nt) {
                    const float2 bv = g_woutF[((size_t)(nt_base + nt)*NKT + ktg)*32 + lane];
                    unsigned b[2] = { fbits(bv.x), fbits(bv.y) };
                    mma_tf32(yacc[0][nt], a[0], b);
                    mma_tf32(yacc[1][nt], a[1], b);
                }
            }
        }
        // no extra sync: next xh-stage writes xh only; its barrier orders these
        // oh reads against the next head's AV writes (3 barriers in between).
    }

    // ---- epilogue: bias + store y[32,256] for this point ----
    #pragma unroll
    for (int nt = 0; nt < 4; ++nt) {
        const int cn = warp*32 + nt*8 + 2*tg;
        float2 bo = *(const float2*)&bout[cn];
        #pragma unroll
        for (int mt = 0; mt < 2; ++mt) {
            const size_t r0 = tok0 + mt*16 + g4;
            *(float2*)&y[r0*DIMC + cn] =
                make_float2(yacc[mt][nt][0] + bo.x, yacc[mt][nt][1] + bo.y);
            *(float2*)&y[(r0+8)*DIMC + cn] =
                make_float2(yacc[mt][nt][2] + bo.x, yacc[mt][nt][3] + bo.y);
        }
    }
}

// ---------------- launcher ----------------
extern "C" void kernel_launch(void* const* d_in, const int* in_sizes, int n_in,
                              void* d_out, int out_size) {
    const float* x     = (const float*)d_in[0];
    const float* gamma = (const float*)d_in[1];
    const float* beta  = (const float*)d_in[2];
    const float* Wq    = (const float*)d_in[3];
    const float* Wk    = (const float*)d_in[4];
    const float* Wv    = (const float*)d_in[5];
    const float* Wout  = (const float*)d_in[6];
    const float* bout  = (const float*)d_in[7];
    float* y = (float*)d_out;

    cudaFuncSetAttribute(fused_all_kernel, cudaFuncAttributeMaxDynamicSharedMemorySize,
                         FUSED_SMEM_BYTES);

    bn_zero_kernel<<<1, 256>>>();
    bn_stats_kernel<<<512, 256>>>((const float4*)x);
    bn_finalize_kernel<<<1, 256>>>(gamma, beta);
    round_weights_kernel<<<(INNERD*DIMC + 255)/256, 256>>>(Wq, Wk, Wv, Wout);
    fused_all_kernel<<<NPTS, 256, FUSED_SMEM_BYTES>>>(x, bout, y);
}

// round 15
// speedup vs baseline: 1.0964x; 1.0964x over previous
#include <cuda_runtime.h>

// Problem constants
#define NB     4
#define NP     1024
#define NKN    32
#define DIMC   256
#define HEADS  8
#define DH     64
#define DPG    32
#define INNERD 512
#define NPTS   (NB*NP)        // 4096 points
#define NTOK   (NPTS*NKN)     // 131072 tokens
#define NKT    (INNERD/8)     // 64 k-tiles

// ---------------- device scratch (no allocations allowed) ----------------
__device__ float g_sum[DIMC];
__device__ float g_sumsq[DIMC];
__device__ float g_scale[DIMC];
__device__ float g_shift[DIMC];
// Wout in mma B-fragment order: [ntile(32)][ktile(64)][lane] float2 (tf32-rounded)
__device__ float2 g_woutF[32 * NKT * 32];         // 512 KB
// QKV weights in mma-fragment order: [h][pr][ntile(8)][kt(4)][lane(32)][2]
#define WFRAG_FLOATS (HEADS*3*8*4*32*2)           // 49152
__device__ float g_wfrag[WFRAG_FLOATS];

// ---------------- tf32 / mma helpers ----------------
__device__ __forceinline__ float tf32r(float x) {
    unsigned u; asm("cvt.rna.tf32.f32 %0, %1;" : "=r"(u) : "f"(x));
    return __uint_as_float(u);
}
__device__ __forceinline__ unsigned fbits(float x) { return __float_as_uint(x); }

__device__ __forceinline__ void mma_tf32(float c[4], const unsigned a[4], const unsigned b[2]) {
    asm volatile("mma.sync.aligned.m16n8k8.row.col.f32.tf32.tf32.f32 "
                 "{%0,%1,%2,%3}, {%4,%5,%6,%7}, {%8,%9}, {%0,%1,%2,%3};"
                 : "+f"(c[0]), "+f"(c[1]), "+f"(c[2]), "+f"(c[3])
                 : "r"(a[0]), "r"(a[1]), "r"(a[2]), "r"(a[3]), "r"(b[0]), "r"(b[1]));
}

// ---------------- K0: zero BN accumulators ----------------
__global__ void bn_zero_kernel() {
    g_sum[threadIdx.x] = 0.f;
    g_sumsq[threadIdx.x] = 0.f;
}

// ---------------- K1: BN statistics ----------------
__global__ __launch_bounds__(256) void bn_stats_kernel(const float4* __restrict__ x4) {
    const int tid = threadIdx.x;
    const int c64 = tid & 63;
    const int rl  = tid >> 6;
    const size_t base = (size_t)blockIdx.x * 256 + (size_t)rl * 64;
    float4 s = make_float4(0.f,0.f,0.f,0.f);
    float4 q = make_float4(0.f,0.f,0.f,0.f);
    #pragma unroll 4
    for (int i = 0; i < 64; ++i) {
        float4 v = x4[(base + i) * 64 + c64];
        s.x += v.x; s.y += v.y; s.z += v.z; s.w += v.w;
        q.x += v.x*v.x; q.y += v.y*v.y; q.z += v.z*v.z; q.w += v.w*v.w;
    }
    __shared__ float4 ss[256], qq[256];
    ss[tid] = s; qq[tid] = q;
    __syncthreads();
    if (tid < 64) {
        float4 a = ss[tid], b = ss[tid+64], c2 = ss[tid+128], d = ss[tid+192];
        float4 e = qq[tid], f = qq[tid+64], g2 = qq[tid+128], h = qq[tid+192];
        atomicAdd(&g_sum[tid*4+0], a.x+b.x+c2.x+d.x);
        atomicAdd(&g_sum[tid*4+1], a.y+b.y+c2.y+d.y);
        atomicAdd(&g_sum[tid*4+2], a.z+b.z+c2.z+d.z);
        atomicAdd(&g_sum[tid*4+3], a.w+b.w+c2.w+d.w);
        atomicAdd(&g_sumsq[tid*4+0], e.x+f.x+g2.x+h.x);
        atomicAdd(&g_sumsq[tid*4+1], e.y+f.y+g2.y+h.y);
        atomicAdd(&g_sumsq[tid*4+2], e.z+f.z+g2.z+h.z);
        atomicAdd(&g_sumsq[tid*4+3], e.w+f.w+g2.w+h.w);
    }
}

// ---------------- K2: BN finalize ----------------
__global__ void bn_finalize_kernel(const float* __restrict__ gamma,
                                   const float* __restrict__ beta) {
    const int c = threadIdx.x;
    const float invN = 1.f / (float)NTOK;
    float m   = g_sum[c] * invN;
    float var = g_sumsq[c] * invN - m * m;
    float rstd = rsqrtf(var + 1e-5f);
    float sc = gamma[c] * rstd;
    g_scale[c] = sc;
    g_shift[c] = beta[c] - m * sc;
}

// ---------------- K2b: pre-round weights; build fragment layouts ----------------
__global__ void round_weights_kernel(const float* __restrict__ Wq,
                                     const float* __restrict__ Wk,
                                     const float* __restrict__ Wv,
                                     const float* __restrict__ Wout) {
    int i = blockIdx.x * 256 + threadIdx.x;
    if (i < INNERD*DIMC) {
        int e    = i & 1;
        int lane = (i >> 1) & 31;
        int kt   = (i >> 6) & 63;
        int nt   = (i >> 12) & 31;
        int k = kt*8 + (lane & 3) + (e ? 4 : 0);
        int n = nt*8 + (lane >> 2);
        ((float*)g_woutF)[i] = tf32r(Wout[k*DIMC + n]);
    }
    if (i < WFRAG_FLOATS) {
        int e    = i & 1;
        int lane = (i >> 1) & 31;
        int kt   = (i >> 6) & 3;
        int nt   = (i >> 8) & 7;
        int pr   = (i >> 11) % 3;
        int h    = i / (3 << 11);
        int o = nt*8 + (lane >> 2);
        int c = kt*8 + (lane & 3) + (e ? 4 : 0);
        const float* src = (pr == 0) ? Wq : (pr == 1) ? Wk : Wv;
        g_wfrag[i] = tf32r(src[h*(DH*DPG) + o*DPG + c]);
    }
}

// ---------------- K3: fully fused, 2 points per block ----------------
// smem floats: xh 64*36 + qs 64*68 + ks 64*68 + vT 64*68 + attnS 64*36 + oh 64*68 = 22016
#define FUSED_SMEM_BYTES (22016 * 4)               // 88064 B -> occ 2

__global__ __launch_bounds__(256, 2) void fused_all2_kernel(
    const float* __restrict__ x,
    const float* __restrict__ bout,
    float* __restrict__ y)
{
    extern __shared__ float sm[];
    float* xh    = sm;                 // [64][36]
    float* qs    = xh + 64*36;         // [64][68]
    float* ks    = qs + 64*68;         // [64][68]
    float* vT    = ks + 64*68;         // [64 out][68] (cols = 64 tokens)
    float* attnS = vT + 64*68;         // [64][36]
    float* oh    = attnS + 64*36;      // [64][68] per-head AV output (both points)

    const int tid  = threadIdx.x;
    const int warp = tid >> 5;
    const int lane = tid & 31;
    const int g4   = lane >> 2;
    const int tg   = lane & 3;
    const size_t tok0 = (size_t)blockIdx.x * 64;   // 2 points = 64 token rows

    float yacc[4][4][4] = {};          // [mtile 0..3][ntile in warp slice][frag]

    for (int h = 0; h < HEADS; ++h) {
        // ---- stage xh (normalize + tf32): 2048 elems / 256 threads ----
        #pragma unroll
        for (int j = 0; j < 8; ++j) {
            int i = tid + j*256;
            int tk = i >> 5, c = i & 31;
            float sc = g_scale[h*32 + c];
            float sh = g_shift[h*32 + c];
            xh[tk*36 + c] = tf32r(fmaf(x[(tok0 + tk)*DIMC + h*32 + c], sc, sh));
        }
        __syncthreads();

        // ---- projections: warp = ntile (8 out cols); M=64 in 2 halves ----
        {
            const int col = warp*8 + 2*tg;
            #pragma unroll
            for (int mh = 0; mh < 2; ++mh) {
                unsigned a[2][4][4];
                #pragma unroll
                for (int mt = 0; mt < 2; ++mt)
                    #pragma unroll
                    for (int kt = 0; kt < 4; ++kt) {
                        const float* ap = &xh[((mh*2 + mt)*16 + g4)*36 + kt*8 + tg];
                        a[mt][kt][0] = fbits(ap[0]);
                        a[mt][kt][1] = fbits(ap[8*36]);
                        a[mt][kt][2] = fbits(ap[4]);
                        a[mt][kt][3] = fbits(ap[8*36 + 4]);
                    }
                #pragma unroll
                for (int pr = 0; pr < 3; ++pr) {
                    unsigned b[4][2];
                    #pragma unroll
                    for (int kt = 0; kt < 4; ++kt) {
                        const float2 v = *(const float2*)
                            &g_wfrag[((((h*3 + pr)*8 + warp)*4 + kt)*32 + lane)*2];
                        b[kt][0] = fbits(v.x);
                        b[kt][1] = fbits(v.y);
                    }
                    float c[2][4] = {};
                    #pragma unroll
                    for (int kt = 0; kt < 4; ++kt) {
                        mma_tf32(c[0], a[0][kt], b[kt]);
                        mma_tf32(c[1], a[1][kt], b[kt]);
                    }
                    if (pr < 2) {
                        float* dst = (pr == 0) ? qs : ks;
                        #pragma unroll
                        for (int mt = 0; mt < 2; ++mt) {
                            int r = (mh*2 + mt)*16 + g4;
                            *(float2*)&dst[r*68 + col]     = make_float2(tf32r(c[mt][0]), tf32r(c[mt][1]));
                            *(float2*)&dst[(r+8)*68 + col] = make_float2(tf32r(c[mt][2]), tf32r(c[mt][3]));
                        }
                    } else {
                        #pragma unroll
                        for (int mt = 0; mt < 2; ++mt) {
                            int r = (mh*2 + mt)*16 + g4;
                            vT[(col  )*68 + r]     = tf32r(c[mt][0]);
                            vT[(col+1)*68 + r]     = tf32r(c[mt][1]);
                            vT[(col  )*68 + r + 8] = tf32r(c[mt][2]);
                            vT[(col+1)*68 + r + 8] = tf32r(c[mt][3]);
                        }
                    }
                }
            }
        }
        __syncthreads();

        // ---- dots: warp -> (point p, mtile, n-half). K=64 (8 ktiles) ----
        {
            const int p  = warp >> 2;
            const int mt = (warp >> 1) & 1;
            const int nh = warp & 1;
            const int rbase = p*32 + mt*16;
            unsigned a[8][4];
            #pragma unroll
            for (int kt = 0; kt < 8; ++kt) {
                const float* ap = &qs[(rbase + g4)*68 + kt*8 + tg];
                a[kt][0] = fbits(ap[0]);
                a[kt][1] = fbits(ap[8*68]);
                a[kt][2] = fbits(ap[4]);
                a[kt][3] = fbits(ap[8*68 + 4]);
            }
            float c[2][4] = {};
            #pragma unroll
            for (int nn = 0; nn < 2; ++nn) {
                const int tokn = p*32 + (nh*2 + nn)*8;
                #pragma unroll
                for (int kt = 0; kt < 8; ++kt) {
                    const float* bp = &ks[(tokn + g4)*68 + kt*8 + tg];
                    unsigned b[2] = { fbits(bp[0]), fbits(bp[4]) };
                    mma_tf32(c[nn], a[kt], b);
                }
            }
            #pragma unroll
            for (int nn = 0; nn < 2; ++nn) {
                const int col = (nh*2 + nn)*8 + 2*tg;
                *(float2*)&attnS[(rbase + g4)*36 + col] =
                    make_float2(c[nn][0]*0.125f, c[nn][1]*0.125f);
                *(float2*)&attnS[(rbase + 8 + g4)*36 + col] =
                    make_float2(c[nn][2]*0.125f, c[nn][3]*0.125f);
            }
        }
        __syncthreads();

        // ---- softmax: warp owns rows warp*8..+8; 4 lanes per row ----
        {
            const int r  = warp*8 + (lane >> 2);
            const int cq = lane & 3;
            float4 v0 = *(const float4*)&attnS[r*36 + cq*8];
            float4 v1 = *(const float4*)&attnS[r*36 + cq*8 + 4];
            float mx = fmaxf(fmaxf(fmaxf(v0.x, v0.y), fmaxf(v0.z, v0.w)),
                             fmaxf(fmaxf(v1.x, v1.y), fmaxf(v1.z, v1.w)));
            mx = fmaxf(mx, __shfl_xor_sync(0xffffffffu, mx, 1));
            mx = fmaxf(mx, __shfl_xor_sync(0xffffffffu, mx, 2));
            float e0 = __expf(v0.x - mx), e1 = __expf(v0.y - mx);
            float e2 = __expf(v0.z - mx), e3 = __expf(v0.w - mx);
            float e4 = __expf(v1.x - mx), e5 = __expf(v1.y - mx);
            float e6 = __expf(v1.z - mx), e7 = __expf(v1.w - mx);
            float s = ((e0+e1)+(e2+e3)) + ((e4+e5)+(e6+e7));
            s += __shfl_xor_sync(0xffffffffu, s, 1);
            s += __shfl_xor_sync(0xffffffffu, s, 2);
            float inv = 1.f / s;
            *(float4*)&attnS[r*36 + cq*8] =
                make_float4(tf32r(e0*inv), tf32r(e1*inv), tf32r(e2*inv), tf32r(e3*inv));
            *(float4*)&attnS[r*36 + cq*8 + 4] =
                make_float4(tf32r(e4*inv), tf32r(e5*inv), tf32r(e6*inv), tf32r(e7*inv));
        }
        __syncthreads();

        // ---- AV: warp -> (point p, mtile, n-quad of 32 cols); writes oh ----
        {
            const int p  = warp >> 2;
            const int mt = (warp >> 1) & 1;
            const int nq = warp & 1;
            const int rbase = p*32 + mt*16;
            unsigned a[4][4];
            #pragma unroll
            for (int kt = 0; kt < 4; ++kt) {
                const float* ap = &attnS[(rbase + g4)*36 + kt*8 + tg];
                a[kt][0] = fbits(ap[0]);
                a[kt][1] = fbits(ap[8*36]);
                a[kt][2] = fbits(ap[4]);
                a[kt][3] = fbits(ap[8*36 + 4]);
            }
            #pragma unroll
            for (int nt = 0; nt < 4; ++nt) {
                const int o = nq*32 + nt*8;
                float c[4] = {};
                #pragma unroll
                for (int kt = 0; kt < 4; ++kt) {
                    const float* bp = &vT[(o + g4)*68 + p*32 + kt*8 + tg];
                    unsigned b[2] = { fbits(bp[0]), fbits(bp[4]) };
                    mma_tf32(c, a[kt], b);
                }
                const int r = rbase + g4, col = o + 2*tg;
                *(float2*)&oh[r*68 + col]     = make_float2(tf32r(c[0]), tf32r(c[1]));
                *(float2*)&oh[(r+8)*68 + col] = make_float2(tf32r(c[2]), tf32r(c[3]));
            }
        }
        __syncthreads();   // oh complete (both points) for this head

        // ---- y-GEMM accumulate: yacc += oh[64,64] @ Wout[h*64:(h+1)*64, warp slice] ----
        // Warp owns n-slice warp*32..+32 (4 ntiles) for ALL 64 rows -> B frag feeds 4 mmas.
        {
            const int nt_base = warp*4;
            #pragma unroll
            for (int kt = 0; kt < 8; ++kt) {
                const int ktg = h*8 + kt;
                unsigned a[4][4];
                #pragma unroll
                for (int mt = 0; mt < 4; ++mt) {
                    const float* ap = &oh[(mt*16 + g4)*68 + kt*8 + tg];
                    a[mt][0] = fbits(ap[0]);
                    a[mt][1] = fbits(ap[8*68]);
                    a[mt][2] = fbits(ap[4]);
                    a[mt][3] = fbits(ap[8*68 + 4]);
                }
                #pragma unroll
                for (int nt = 0; nt < 4; ++nt) {
                    const float2 bv = g_woutF[((size_t)(nt_base + nt)*NKT + ktg)*32 + lane];
                    unsigned b[2] = { fbits(bv.x), fbits(bv.y) };
                    #pragma unroll
                    for (int mt = 0; mt < 4; ++mt)
                        mma_tf32(yacc[mt][nt], a[mt], b);
                }
            }
        }
        // no trailing barrier: 4 barriers separate these oh reads from next AV write.
    }

    // ---- epilogue: bias + store y[64,256] ----
    #pragma unroll
    for (int nt = 0; nt < 4; ++nt) {
        const int cn = warp*32 + nt*8 + 2*tg;
        float2 bo = *(const float2*)&bout[cn];
        #pragma unroll
        for (int mt = 0; mt < 4; ++mt) {
            const size_t r0 = tok0 + mt*16 + g4;
            *(float2*)&y[r0*DIMC + cn] =
                make_float2(yacc[mt][nt][0] + bo.x, yacc[mt][nt][1] + bo.y);
            *(float2*)&y[(r0+8)*DIMC + cn] =
                make_float2(yacc[mt][nt][2] + bo.x, yacc[mt][nt][3] + bo.y);
        }
    }
}

// ---------------- launcher ----------------
extern "C" void kernel_launch(void* const* d_in, const int* in_sizes, int n_in,
                              void* d_out, int out_size) {
    const float* x     = (const float*)d_in[0];
    const float* gamma = (const float*)d_in[1];
    const float* beta  = (const float*)d_in[2];
    const float* Wq    = (const float*)d_in[3];
    const float* Wk    = (const float*)d_in[4];
    const float* Wv    = (const float*)d_in[5];
    const float* Wout  = (const float*)d_in[6];
    const float* bout  = (const float*)d_in[7];
    float* y = (float*)d_out;

    cudaFuncSetAttribute(fused_all2_kernel, cudaFuncAttributeMaxDynamicSharedMemorySize,
                         FUSED_SMEM_BYTES);

    bn_zero_kernel<<<1, 256>>>();
    bn_stats_kernel<<<512, 256>>>((const float4*)x);
    bn_finalize_kernel<<<1, 256>>>(gamma, beta);
    round_weights_kernel<<<(INNERD*DIMC + 255)/256, 256>>>(Wq, Wk, Wv, Wout);
    fused_all2_kernel<<<NPTS/2, 256, FUSED_SMEM_BYTES>>>(x, bout, y);
}

// round 16
// speedup vs baseline: 1.1227x; 1.0240x over previous
#include <cuda_runtime.h>

// Problem constants
#define NB     4
#define NP     1024
#define NKN    32
#define DIMC   256
#define HEADS  8
#define DH     64
#define DPG    32
#define INNERD 512
#define NPTS   (NB*NP)        // 4096 points
#define NTOK   (NPTS*NKN)     // 131072 tokens
#define NKT    (INNERD/8)     // 64 k-tiles

// ---------------- device scratch (no allocations allowed) ----------------
__device__ float g_sum[DIMC];
__device__ float g_sumsq[DIMC];
__device__ float g_scale[DIMC];
__device__ float g_shift[DIMC];
// Wout in mma B-fragment order: [ntile(32)][ktile(64)][lane] float2 (tf32-rounded)
__device__ float2 g_woutF[32 * NKT * 32];         // 512 KB
// QKV weights in mma-fragment order: [h][pr][ntile(8)][kt(4)][lane(32)][2]
#define WFRAG_FLOATS (HEADS*3*8*4*32*2)           // 49152
__device__ float g_wfrag[WFRAG_FLOATS];

// ---------------- tf32 / mma helpers ----------------
__device__ __forceinline__ float tf32r(float x) {
    unsigned u; asm("cvt.rna.tf32.f32 %0, %1;" : "=r"(u) : "f"(x));
    return __uint_as_float(u);
}
__device__ __forceinline__ unsigned fbits(float x) { return __float_as_uint(x); }

__device__ __forceinline__ void mma_tf32(float c[4], const unsigned a[4], const unsigned b[2]) {
    asm volatile("mma.sync.aligned.m16n8k8.row.col.f32.tf32.tf32.f32 "
                 "{%0,%1,%2,%3}, {%4,%5,%6,%7}, {%8,%9}, {%0,%1,%2,%3};"
                 : "+f"(c[0]), "+f"(c[1]), "+f"(c[2]), "+f"(c[3])
                 : "r"(a[0]), "r"(a[1]), "r"(a[2]), "r"(a[3]), "r"(b[0]), "r"(b[1]));
}

// ---------------- K0: zero BN accumulators ----------------
__global__ void bn_zero_kernel() {
    g_sum[threadIdx.x] = 0.f;
    g_sumsq[threadIdx.x] = 0.f;
}

// ---------------- K1: BN statistics ----------------
__global__ __launch_bounds__(256) void bn_stats_kernel(const float4* __restrict__ x4) {
    const int tid = threadIdx.x;
    const int c64 = tid & 63;
    const int rl  = tid >> 6;
    const size_t base = (size_t)blockIdx.x * 256 + (size_t)rl * 64;
    float4 s = make_float4(0.f,0.f,0.f,0.f);
    float4 q = make_float4(0.f,0.f,0.f,0.f);
    #pragma unroll 4
    for (int i = 0; i < 64; ++i) {
        float4 v = x4[(base + i) * 64 + c64];
        s.x += v.x; s.y += v.y; s.z += v.z; s.w += v.w;
        q.x += v.x*v.x; q.y += v.y*v.y; q.z += v.z*v.z; q.w += v.w*v.w;
    }
    __shared__ float4 ss[256], qq[256];
    ss[tid] = s; qq[tid] = q;
    __syncthreads();
    if (tid < 64) {
        float4 a = ss[tid], b = ss[tid+64], c2 = ss[tid+128], d = ss[tid+192];
        float4 e = qq[tid], f = qq[tid+64], g2 = qq[tid+128], h = qq[tid+192];
        atomicAdd(&g_sum[tid*4+0], a.x+b.x+c2.x+d.x);
        atomicAdd(&g_sum[tid*4+1], a.y+b.y+c2.y+d.y);
        atomicAdd(&g_sum[tid*4+2], a.z+b.z+c2.z+d.z);
        atomicAdd(&g_sum[tid*4+3], a.w+b.w+c2.w+d.w);
        atomicAdd(&g_sumsq[tid*4+0], e.x+f.x+g2.x+h.x);
        atomicAdd(&g_sumsq[tid*4+1], e.y+f.y+g2.y+h.y);
        atomicAdd(&g_sumsq[tid*4+2], e.z+f.z+g2.z+h.z);
        atomicAdd(&g_sumsq[tid*4+3], e.w+f.w+g2.w+h.w);
    }
}

// ---------------- K2: BN finalize ----------------
__global__ void bn_finalize_kernel(const float* __restrict__ gamma,
                                   const float* __restrict__ beta) {
    const int c = threadIdx.x;
    const float invN = 1.f / (float)NTOK;
    float m   = g_sum[c] * invN;
    float var = g_sumsq[c] * invN - m * m;
    float rstd = rsqrtf(var + 1e-5f);
    float sc = gamma[c] * rstd;
    g_scale[c] = sc;
    g_shift[c] = beta[c] - m * sc;
}

// ---------------- K2b: pre-round weights; build fragment layouts ----------------
__global__ void round_weights_kernel(const float* __restrict__ Wq,
                                     const float* __restrict__ Wk,
                                     const float* __restrict__ Wv,
                                     const float* __restrict__ Wout) {
    int i = blockIdx.x * 256 + threadIdx.x;
    if (i < INNERD*DIMC) {
        int e    = i & 1;
        int lane = (i >> 1) & 31;
        int kt   = (i >> 6) & 63;
        int nt   = (i >> 12) & 31;
        int k = kt*8 + (lane & 3) + (e ? 4 : 0);
        int n = nt*8 + (lane >> 2);
        ((float*)g_woutF)[i] = tf32r(Wout[k*DIMC + n]);
    }
    if (i < WFRAG_FLOATS) {
        int e    = i & 1;
        int lane = (i >> 1) & 31;
        int kt   = (i >> 6) & 3;
        int nt   = (i >> 8) & 7;
        int pr   = (i >> 11) % 3;
        int h    = i / (3 << 11);
        int o = nt*8 + (lane >> 2);
        int c = kt*8 + (lane & 3) + (e ? 4 : 0);
        const float* src = (pr == 0) ? Wq : (pr == 1) ? Wk : Wv;
        g_wfrag[i] = tf32r(src[h*(DH*DPG) + o*DPG + c]);
    }
}

// ---------------- K3: fully fused, 2 points per block, xh double-buffered ----------------
// smem floats: xh 2*64*36 + qs 64*68 + ks 64*68 + vT 64*68 + attnS 64*36 + oh 64*68 = 24320
#define FUSED_SMEM_BYTES (24320 * 4)               // 97280 B -> occ 2

__global__ __launch_bounds__(256, 2) void fused_all3_kernel(
    const float* __restrict__ x,
    const float* __restrict__ bout,
    float* __restrict__ y)
{
    extern __shared__ float sm[];
    float* xh0   = sm;                 // [2][64][36]
    float* qs    = xh0 + 2*64*36;      // [64][68]
    float* ks    = qs + 64*68;         // [64][68]
    float* vT    = ks + 64*68;         // [64 out][68] (cols = 64 tokens)
    float* attnS = vT + 64*68;         // [64][36]
    float* oh    = attnS + 64*36;      // [64][68] per-head AV output

    const int tid  = threadIdx.x;
    const int warp = tid >> 5;
    const int lane = tid & 31;
    const int g4   = lane >> 2;
    const int tg   = lane & 3;
    const size_t tok0 = (size_t)blockIdx.x * 64;   // 2 points = 64 token rows

    float yacc[4][4][4] = {};          // [mtile][ntile in warp slice][frag]

    // ---- pre-loop: stage xh buffer 0 for h=0 ----
    #pragma unroll
    for (int j = 0; j < 8; ++j) {
        int i = tid + j*256;
        int tk = i >> 5, c = i & 31;
        xh0[tk*36 + c] = tf32r(fmaf(x[(tok0 + tk)*DIMC + c], g_scale[c], g_shift[c]));
    }
    __syncthreads();

    for (int h = 0; h < HEADS; ++h) {
        const float* xh = xh0 + (h & 1)*2304;

        // ---- projections: warp = ntile (8 out cols); M=64 in 2 halves ----
        {
            const int col = warp*8 + 2*tg;
            #pragma unroll
            for (int mh = 0; mh < 2; ++mh) {
                unsigned a[2][4][4];
                #pragma unroll
                for (int mt = 0; mt < 2; ++mt)
                    #pragma unroll
                    for (int kt = 0; kt < 4; ++kt) {
                        const float* ap = &xh[((mh*2 + mt)*16 + g4)*36 + kt*8 + tg];
                        a[mt][kt][0] = fbits(ap[0]);
                        a[mt][kt][1] = fbits(ap[8*36]);
                        a[mt][kt][2] = fbits(ap[4]);
                        a[mt][kt][3] = fbits(ap[8*36 + 4]);
                    }
                #pragma unroll
                for (int pr = 0; pr < 3; ++pr) {
                    unsigned b[4][2];
                    #pragma unroll
                    for (int kt = 0; kt < 4; ++kt) {
                        const float2 v = *(const float2*)
                            &g_wfrag[((((h*3 + pr)*8 + warp)*4 + kt)*32 + lane)*2];
                        b[kt][0] = fbits(v.x);
                        b[kt][1] = fbits(v.y);
                    }
                    float c[2][4] = {};
                    #pragma unroll
                    for (int kt = 0; kt < 4; ++kt) {
                        mma_tf32(c[0], a[0][kt], b[kt]);
                        mma_tf32(c[1], a[1][kt], b[kt]);
                    }
                    if (pr < 2) {
                        float* dst = (pr == 0) ? qs : ks;
                        #pragma unroll
                        for (int mt = 0; mt < 2; ++mt) {
                            int r = (mh*2 + mt)*16 + g4;
                            *(float2*)&dst[r*68 + col]     = make_float2(tf32r(c[mt][0]), tf32r(c[mt][1]));
                            *(float2*)&dst[(r+8)*68 + col] = make_float2(tf32r(c[mt][2]), tf32r(c[mt][3]));
                        }
                    } else {
                        #pragma unroll
                        for (int mt = 0; mt < 2; ++mt) {
                            int r = (mh*2 + mt)*16 + g4;
                            vT[(col  )*68 + r]     = tf32r(c[mt][0]);
                            vT[(col+1)*68 + r]     = tf32r(c[mt][1]);
                            vT[(col  )*68 + r + 8] = tf32r(c[mt][2]);
                            vT[(col+1)*68 + r + 8] = tf32r(c[mt][3]);
                        }
                    }
                }
            }
        }
        __syncthreads();   // bar1

        // ---- dots: warp -> (point p, mtile, n-half). K=64 (8 ktiles) ----
        {
            const int p  = warp >> 2;
            const int mt = (warp >> 1) & 1;
            const int nh = warp & 1;
            const int rbase = p*32 + mt*16;
            unsigned a[8][4];
            #pragma unroll
            for (int kt = 0; kt < 8; ++kt) {
                const float* ap = &qs[(rbase + g4)*68 + kt*8 + tg];
                a[kt][0] = fbits(ap[0]);
                a[kt][1] = fbits(ap[8*68]);
                a[kt][2] = fbits(ap[4]);
                a[kt][3] = fbits(ap[8*68 + 4]);
            }
            float c[2][4] = {};
            #pragma unroll
            for (int nn = 0; nn < 2; ++nn) {
                const int tokn = p*32 + (nh*2 + nn)*8;
                #pragma unroll
                for (int kt = 0; kt < 8; ++kt) {
                    const float* bp = &ks[(tokn + g4)*68 + kt*8 + tg];
                    unsigned b[2] = { fbits(bp[0]), fbits(bp[4]) };
                    mma_tf32(c[nn], a[kt], b);
                }
            }
            #pragma unroll
            for (int nn = 0; nn < 2; ++nn) {
                const int col = (nh*2 + nn)*8 + 2*tg;
                *(float2*)&attnS[(rbase + g4)*36 + col] =
                    make_float2(c[nn][0]*0.125f, c[nn][1]*0.125f);
                *(float2*)&attnS[(rbase + 8 + g4)*36 + col] =
                    make_float2(c[nn][2]*0.125f, c[nn][3]*0.125f);
            }
        }
        __syncthreads();   // bar2

        // ---- softmax: warp owns rows warp*8..+8; 4 lanes per row ----
        {
            const int r  = warp*8 + (lane >> 2);
            const int cq = lane & 3;
            float4 v0 = *(const float4*)&attnS[r*36 + cq*8];
            float4 v1 = *(const float4*)&attnS[r*36 + cq*8 + 4];
            float mx = fmaxf(fmaxf(fmaxf(v0.x, v0.y), fmaxf(v0.z, v0.w)),
                             fmaxf(fmaxf(v1.x, v1.y), fmaxf(v1.z, v1.w)));
            mx = fmaxf(mx, __shfl_xor_sync(0xffffffffu, mx, 1));
            mx = fmaxf(mx, __shfl_xor_sync(0xffffffffu, mx, 2));
            float e0 = __expf(v0.x - mx), e1 = __expf(v0.y - mx);
            float e2 = __expf(v0.z - mx), e3 = __expf(v0.w - mx);
            float e4 = __expf(v1.x - mx), e5 = __expf(v1.y - mx);
            float e6 = __expf(v1.z - mx), e7 = __expf(v1.w - mx);
            float s = ((e0+e1)+(e2+e3)) + ((e4+e5)+(e6+e7));
            s += __shfl_xor_sync(0xffffffffu, s, 1);
            s += __shfl_xor_sync(0xffffffffu, s, 2);
            float inv = 1.f / s;
            *(float4*)&attnS[r*36 + cq*8] =
                make_float4(tf32r(e0*inv), tf32r(e1*inv), tf32r(e2*inv), tf32r(e3*inv));
            *(float4*)&attnS[r*36 + cq*8 + 4] =
                make_float4(tf32r(e4*inv), tf32r(e5*inv), tf32r(e6*inv), tf32r(e7*inv));
        }
        __syncthreads();   // bar3

        // ---- AV (+ prefetch x for head h+1, hidden behind AV mmas) ----
        {
            // issue prefetch LDGs first (DRAM latency overlaps AV compute)
            float xpre[8];
            if (h + 1 < HEADS) {
                #pragma unroll
                for (int j = 0; j < 8; ++j) {
                    int i = tid + j*256;
                    int tk = i >> 5, c = i & 31;
                    xpre[j] = x[(tok0 + tk)*DIMC + (h+1)*32 + c];
                }
            }

            const int p  = warp >> 2;
            const int mt = (warp >> 1) & 1;
            const int nq = warp & 1;
            const int rbase = p*32 + mt*16;
            unsigned a[4][4];
            #pragma unroll
            for (int kt = 0; kt < 4; ++kt) {
                const float* ap = &attnS[(rbase + g4)*36 + kt*8 + tg];
                a[kt][0] = fbits(ap[0]);
                a[kt][1] = fbits(ap[8*36]);
                a[kt][2] = fbits(ap[4]);
                a[kt][3] = fbits(ap[8*36 + 4]);
            }
            #pragma unroll
            for (int nt = 0; nt < 4; ++nt) {
                const int o = nq*32 + nt*8;
                float c[4] = {};
                #pragma unroll
                for (int kt = 0; kt < 4; ++kt) {
                    const float* bp = &vT[(o + g4)*68 + p*32 + kt*8 + tg];
                    unsigned b[2] = { fbits(bp[0]), fbits(bp[4]) };
                    mma_tf32(c, a[kt], b);
                }
                const int r = rbase + g4, col = o + 2*tg;
                *(float2*)&oh[r*68 + col]     = make_float2(tf32r(c[0]), tf32r(c[1]));
                *(float2*)&oh[(r+8)*68 + col] = make_float2(tf32r(c[2]), tf32r(c[3]));
            }

            // store normalized next-head xh into the other buffer
            if (h + 1 < HEADS) {
                float* xnx = xh0 + ((h+1) & 1)*2304;
                #pragma unroll
                for (int j = 0; j < 8; ++j) {
                    int i = tid + j*256;
                    int tk = i >> 5, c = i & 31;
                    xnx[tk*36 + c] = tf32r(fmaf(xpre[j], g_scale[(h+1)*32 + c],
                                                g_shift[(h+1)*32 + c]));
                }
            }
        }
        __syncthreads();   // bar4: oh + next xh ready

        // ---- y-GEMM accumulate: yacc += oh[64,64] @ Wout[h*64:(h+1)*64, warp slice] ----
        {
            const int nt_base = warp*4;
            #pragma unroll
            for (int kt = 0; kt < 8; ++kt) {
                const int ktg = h*8 + kt;
                unsigned a[4][4];
                #pragma unroll
                for (int mt = 0; mt < 4; ++mt) {
                    const float* ap = &oh[(mt*16 + g4)*68 + kt*8 + tg];
                    a[mt][0] = fbits(ap[0]);
                    a[mt][1] = fbits(ap[8*68]);
                    a[mt][2] = fbits(ap[4]);
                    a[mt][3] = fbits(ap[8*68 + 4]);
                }
                #pragma unroll
                for (int nt = 0; nt < 4; ++nt) {
                    const float2 bv = g_woutF[((size_t)(nt_base + nt)*NKT + ktg)*32 + lane];
                    unsigned b[2] = { fbits(bv.x), fbits(bv.y) };
                    #pragma unroll
                    for (int mt = 0; mt < 4; ++mt)
                        mma_tf32(yacc[mt][nt], a[mt], b);
                }
            }
        }
        // no trailing barrier: bar1..bar3 of next head separate oh reads from next AV writes,
        // and proj's qs/ks/vT writes happen after bar4 in every thread.
    }

    // ---- epilogue: bias + store y[64,256] ----
    #pragma unroll
    for (int nt = 0; nt < 4; ++nt) {
        const int cn = warp*32 + nt*8 + 2*tg;
        float2 bo = *(const float2*)&bout[cn];
        #pragma unroll
        for (int mt = 0; mt < 4; ++mt) {
            const size_t r0 = tok0 + mt*16 + g4;
            *(float2*)&y[r0*DIMC + cn] =
                make_float2(yacc[mt][nt][0] + bo.x, yacc[mt][nt][1] + bo.y);
            *(float2*)&y[(r0+8)*DIMC + cn] =
                make_float2(yacc[mt][nt][2] + bo.x, yacc[mt][nt][3] + bo.y);
        }
    }
}

// ---------------- launcher ----------------
extern "C" void kernel_launch(void* const* d_in, const int* in_sizes, int n_in,
                              void* d_out, int out_size) {
    const float* x     = (const float*)d_in[0];
    const float* gamma = (const float*)d_in[1];
    const float* beta  = (const float*)d_in[2];
    const float* Wq    = (const float*)d_in[3];
    const float* Wk    = (const float*)d_in[4];
    const float* Wv    = (const float*)d_in[5];
    const float* Wout  = (const float*)d_in[6];
    const float* bout  = (const float*)d_in[7];
    float* y = (float*)d_out;

    cudaFuncSetAttribute(fused_all3_kernel, cudaFuncAttributeMaxDynamicSharedMemorySize,
                         FUSED_SMEM_BYTES);

    bn_zero_kernel<<<1, 256>>>();
    bn_stats_kernel<<<512, 256>>>((const float4*)x);
    bn_finalize_kernel<<<1, 256>>>(gamma, beta);
    round_weights_kernel<<<(INNERD*DIMC + 255)/256, 256>>>(Wq, Wk, Wv, Wout);
    fused_all3_kernel<<<NPTS/2, 256, FUSED_SMEM_BYTES>>>(x, bout, y);
}